// round 9
// baseline (speedup 1.0000x reference)
#include <cuda_runtime.h>
#include <cuda_fp16.h>
#include <math.h>

#define Nn 100000
#define Ee 1600000
#define Kin 128
#define Dd 256

// ---------------- scratch (device globals: no allocation allowed) ----------
__device__ __half g_h16[(size_t)Nn * Dd];  // 51.2 MB projected features (fp16)
__device__ float g_as[Nn * 4];             // a_src per node/head
__device__ float g_ad[Nn * 4];             // a_dst per node/head
__device__ int   g_deg[Nn];                // zero-init; scan re-zeroes each call
__device__ int   g_off[Nn + 1];
__device__ int   g_cur[Nn];
__device__ int   g_csr[Ee];                // src ids grouped by dst

// ---------------- helpers ---------------------------------------------------
__device__ __forceinline__ float lrelu(float v) { return v > 0.f ? v : 0.2f * v; }
__device__ __forceinline__ float selh(const float4& v, int h) {
    return h == 0 ? v.x : (h == 1 ? v.y : (h == 2 ? v.z : v.w));
}
__device__ __forceinline__ void accum8(float* acc, const uint4& hv, float a) {
    float2 f;
    f = __half22float2(*(const __half2*)&hv.x); acc[0] += f.x * a; acc[1] += f.y * a;
    f = __half22float2(*(const __half2*)&hv.y); acc[2] += f.x * a; acc[3] += f.y * a;
    f = __half22float2(*(const __half2*)&hv.z); acc[4] += f.x * a; acc[5] += f.y * a;
    f = __half22float2(*(const __half2*)&hv.w); acc[6] += f.x * a; acc[7] += f.y * a;
}
__device__ __forceinline__ unsigned int to_tf32(float f) {
    unsigned int r;
    asm("cvt.rna.tf32.f32 %0, %1;" : "=r"(r) : "f"(f));
    return r;
}
__device__ __forceinline__ void mma_tf32(float* c,
                                         const unsigned int* a,
                                         const unsigned int* b) {
    asm volatile(
        "mma.sync.aligned.m16n8k8.row.col.f32.tf32.tf32.f32 "
        "{%0,%1,%2,%3}, {%4,%5,%6,%7}, {%8,%9}, {%0,%1,%2,%3};"
        : "+f"(c[0]), "+f"(c[1]), "+f"(c[2]), "+f"(c[3])
        : "r"(a[0]), "r"(a[1]), "r"(a[2]), "r"(a[3]),
          "r"(b[0]), "r"(b[1]));
}

// ---------------- tf32 tensor GEMM + fused attention dots -------------------
__global__ __launch_bounds__(256, 2)
void gemm_att_kernel(const float* __restrict__ x, const float* __restrict__ W,
                     const float* __restrict__ att_src,
                     const float* __restrict__ att_dst) {
    __shared__ float xs[128][36];   // [m][k]
    __shared__ float ws[32][136];   // [k][n]
    const int m0 = blockIdx.x * 128;
    const int c0 = blockIdx.y * 128;
    const int tid = threadIdx.x;
    const int warp = tid >> 5, lane = tid & 31;
    const int g = lane >> 2, tig = lane & 3;
    const int wm = (warp & 3) * 32;
    const int wn = (warp >> 2) * 64;

    float acc[2][8][4];
    #pragma unroll
    for (int mt = 0; mt < 2; ++mt)
        #pragma unroll
        for (int nn = 0; nn < 8; ++nn)
            #pragma unroll
            for (int j = 0; j < 4; ++j) acc[mt][nn][j] = 0.f;

    const int xr = tid >> 1, xc = (tid & 1) * 16;
    const int wk = tid >> 3, wc = (tid & 7) * 16;

    for (int kt = 0; kt < 4; ++kt) {
        float4 xv[4], wv[4];
        #pragma unroll
        for (int i = 0; i < 4; ++i) {
            xv[i] = make_float4(0.f, 0.f, 0.f, 0.f);
            if (m0 + xr < Nn)
                xv[i] = *(const float4*)(x + (size_t)(m0 + xr) * Kin + kt * 32 + xc + i * 4);
            wv[i] = *(const float4*)(W + (size_t)(kt * 32 + wk) * Dd + c0 + wc + i * 4);
        }
        __syncthreads();
        #pragma unroll
        for (int i = 0; i < 4; ++i) {
            *(float4*)&xs[xr][xc + i * 4] = xv[i];
            *(float4*)&ws[wk][wc + i * 4] = wv[i];
        }
        __syncthreads();

        #pragma unroll
        for (int ks = 0; ks < 4; ++ks) {
            const int kb = ks * 8;
            unsigned int a[2][4], b[8][2];
            #pragma unroll
            for (int mt = 0; mt < 2; ++mt) {
                const int r = wm + mt * 16 + g;
                a[mt][0] = to_tf32(xs[r][kb + tig]);
                a[mt][1] = to_tf32(xs[r + 8][kb + tig]);
                a[mt][2] = to_tf32(xs[r][kb + tig + 4]);
                a[mt][3] = to_tf32(xs[r + 8][kb + tig + 4]);
            }
            #pragma unroll
            for (int nn = 0; nn < 8; ++nn) {
                const int c = wn + nn * 8 + g;
                b[nn][0] = to_tf32(ws[kb + tig][c]);
                b[nn][1] = to_tf32(ws[kb + tig + 4][c]);
            }
            #pragma unroll
            for (int mt = 0; mt < 2; ++mt)
                #pragma unroll
                for (int nn = 0; nn < 8; ++nn)
                    mma_tf32(acc[mt][nn], a[mt], b[nn]);
        }
    }

    const int head = blockIdx.y * 2 + (warp >> 2);
    #pragma unroll
    for (int mt = 0; mt < 2; ++mt) {
        const int r0 = m0 + wm + mt * 16 + g;
        const int r1 = r0 + 8;
        float s0 = 0.f, d0 = 0.f, s1 = 0.f, d1 = 0.f;
        #pragma unroll
        for (int nn = 0; nn < 8; ++nn) {
            const int cl = nn * 8 + tig * 2;
            const float as0 = att_src[head * 64 + cl];
            const float as1 = att_src[head * 64 + cl + 1];
            const float ad0 = att_dst[head * 64 + cl];
            const float ad1 = att_dst[head * 64 + cl + 1];
            const float* cc = acc[mt][nn];
            s0 += cc[0] * as0 + cc[1] * as1;
            d0 += cc[0] * ad0 + cc[1] * ad1;
            s1 += cc[2] * as0 + cc[3] * as1;
            d1 += cc[2] * ad0 + cc[3] * ad1;
            const int gc = c0 + wn + cl;
            if (r0 < Nn)
                *(__half2*)(g_h16 + (size_t)r0 * Dd + gc) = __floats2half2_rn(cc[0], cc[1]);
            if (r1 < Nn)
                *(__half2*)(g_h16 + (size_t)r1 * Dd + gc) = __floats2half2_rn(cc[2], cc[3]);
        }
        #pragma unroll
        for (int o = 1; o <= 2; o <<= 1) {
            s0 += __shfl_xor_sync(0xffffffffu, s0, o);
            d0 += __shfl_xor_sync(0xffffffffu, d0, o);
            s1 += __shfl_xor_sync(0xffffffffu, s1, o);
            d1 += __shfl_xor_sync(0xffffffffu, d1, o);
        }
        if (tig == 0) {
            if (r0 < Nn) { g_as[r0 * 4 + head] = s0; g_ad[r0 * 4 + head] = d0; }
            if (r1 < Nn) { g_as[r1 * 4 + head] = s1; g_ad[r1 * 4 + head] = d1; }
        }
    }
}

// ---------------- CSR build -------------------------------------------------
__global__ void degree_kernel(const int* __restrict__ ei) {
    int e = blockIdx.x * blockDim.x + threadIdx.x;
    if (e < Ee) atomicAdd(&g_deg[ei[Ee + e]], 1);
}

__global__ void scan_kernel() {
    __shared__ int ssum[1024];
    const int t = threadIdx.x;
    const int C = 98;  // 1024*98 >= 100000
    int base = t * C;
    int s = 0;
    for (int j = 0; j < C; ++j) {
        int idx = base + j;
        if (idx < Nn) s += g_deg[idx];
    }
    ssum[t] = s;
    __syncthreads();
    for (int off = 1; off < 1024; off <<= 1) {
        int add = (t >= off) ? ssum[t - off] : 0;
        __syncthreads();
        ssum[t] += add;
        __syncthreads();
    }
    int run = (t == 0) ? 0 : ssum[t - 1];
    for (int j = 0; j < C; ++j) {
        int idx = base + j;
        if (idx < Nn) {
            int dv = g_deg[idx];
            g_off[idx] = run;
            g_cur[idx] = run;
            run += dv;
            g_deg[idx] = 0;   // ready for next call
        }
    }
    if (t == 1023) g_off[Nn] = ssum[1023];
}

__global__ void scatter_kernel(const int* __restrict__ ei) {
    int e = blockIdx.x * blockDim.x + threadIdx.x;
    if (e >= Ee) return;
    int s = ei[e];
    int d = ei[Ee + e];
    int pos = atomicAdd(&g_cur[d], 1);
    g_csr[pos] = s;
}

// ---------------- single-pass gather, index-prefetch pipelined --------------
// The csr->data address dependency is bridged across iterations: chunk k's
// data loads use indices fetched during chunk k-1, so each iteration exposes
// ONE memory latency instead of two serialized ones.
__global__ __launch_bounds__(256)
void gather_kernel(const float* __restrict__ bias,
                   const float* __restrict__ gamma,
                   const float* __restrict__ beta,
                   float* __restrict__ out) {
    const int w = threadIdx.x >> 5;
    const int lane = threadIdx.x & 31;
    const int n = blockIdx.x * 8 + w;
    if (n >= Nn) return;

    const int hL = lane >> 3;   // lane owns channels [lane*8, +8) = one head
    const float4 as4 = *(const float4*)(g_as + n * 4);
    const float4 ad4 = *(const float4*)(g_ad + n * 4);
    const float adL = selh(ad4, hL);
    const int off0 = g_off[n], off1 = g_off[n + 1];

    const __half* hbase = g_h16;
    const size_t laneoff = (size_t)lane * 8;

    float acc[8] = {0.f, 0.f, 0.f, 0.f, 0.f, 0.f, 0.f, 0.f};
    float den;
    {   // self loop
        den = __expf(lrelu(selh(as4, hL) + adL));
        uint4 hv = *(const uint4*)(hbase + (size_t)n * Dd + laneoff);
        accum8(acc, hv, den);
    }

    int i = off0;
    int i0 = n, i1 = n, i2 = n, i3 = n;
    if (i + 4 <= off1) {   // prologue: first chunk's indices
        i0 = g_csr[i]; i1 = g_csr[i + 1]; i2 = g_csr[i + 2]; i3 = g_csr[i + 3];
    }
    while (i + 4 <= off1) {
        // data loads for current chunk (addresses already resolved)
        const float4 p0 = *(const float4*)(g_as + i0 * 4);
        const float4 p1 = *(const float4*)(g_as + i1 * 4);
        const float4 p2 = *(const float4*)(g_as + i2 * 4);
        const float4 p3 = *(const float4*)(g_as + i3 * 4);
        const uint4 v0 = *(const uint4*)(hbase + (size_t)i0 * Dd + laneoff);
        const uint4 v1 = *(const uint4*)(hbase + (size_t)i1 * Dd + laneoff);
        const uint4 v2 = *(const uint4*)(hbase + (size_t)i2 * Dd + laneoff);
        const uint4 v3 = *(const uint4*)(hbase + (size_t)i3 * Dd + laneoff);
        // prefetch next chunk's indices (independent, issues before the wait)
        const int ni = i + 4;
        int j0 = i0, j1 = i1, j2 = i2, j3 = i3;
        if (ni + 4 <= off1) {
            j0 = g_csr[ni];     j1 = g_csr[ni + 1];
            j2 = g_csr[ni + 2]; j3 = g_csr[ni + 3];
        }
        // consume
        const float a0 = __expf(lrelu(selh(p0, hL) + adL));
        const float a1 = __expf(lrelu(selh(p1, hL) + adL));
        const float a2 = __expf(lrelu(selh(p2, hL) + adL));
        const float a3 = __expf(lrelu(selh(p3, hL) + adL));
        den += a0 + a1 + a2 + a3;
        accum8(acc, v0, a0);
        accum8(acc, v1, a1);
        accum8(acc, v2, a2);
        accum8(acc, v3, a3);
        i = ni; i0 = j0; i1 = j1; i2 = j2; i3 = j3;
    }
    for (; i < off1; ++i) {
        const int src = g_csr[i];
        const float4 p = *(const float4*)(g_as + src * 4);
        const uint4 v = *(const uint4*)(hbase + (size_t)src * Dd + laneoff);
        const float a = __expf(lrelu(selh(p, hL) + adL));
        den += a;
        accum8(acc, v, a);
    }

    const float rdL = 1.f / den;

    // ---- epilogue: bias + ELU + LayerNorm ----
    const float4 b0 = *(const float4*)(bias + lane * 8);
    const float4 b1 = *(const float4*)(bias + lane * 8 + 4);
    float v[8];
    v[0] = acc[0] * rdL + b0.x; v[1] = acc[1] * rdL + b0.y;
    v[2] = acc[2] * rdL + b0.z; v[3] = acc[3] * rdL + b0.w;
    v[4] = acc[4] * rdL + b1.x; v[5] = acc[5] * rdL + b1.y;
    v[6] = acc[6] * rdL + b1.z; v[7] = acc[7] * rdL + b1.w;
    float sum = 0.f, sq = 0.f;
    #pragma unroll
    for (int j = 0; j < 8; ++j) {
        v[j] = v[j] > 0.f ? v[j] : expm1f(v[j]);
        sum += v[j];
        sq += v[j] * v[j];
    }
    #pragma unroll
    for (int o = 16; o; o >>= 1) {
        sum += __shfl_xor_sync(0xffffffffu, sum, o);
        sq  += __shfl_xor_sync(0xffffffffu, sq, o);
    }
    const float mean = sum * (1.f / 256.f);
    const float var = sq * (1.f / 256.f) - mean * mean;
    const float rstd = rsqrtf(var + 1e-5f);

    const float4 g0 = *(const float4*)(gamma + lane * 8);
    const float4 g1 = *(const float4*)(gamma + lane * 8 + 4);
    const float4 be0 = *(const float4*)(beta + lane * 8);
    const float4 be1 = *(const float4*)(beta + lane * 8 + 4);
    float4 o0, o1;
    o0.x = (v[0] - mean) * rstd * g0.x + be0.x;
    o0.y = (v[1] - mean) * rstd * g0.y + be0.y;
    o0.z = (v[2] - mean) * rstd * g0.z + be0.z;
    o0.w = (v[3] - mean) * rstd * g0.w + be0.w;
    o1.x = (v[4] - mean) * rstd * g1.x + be1.x;
    o1.y = (v[5] - mean) * rstd * g1.y + be1.y;
    o1.z = (v[6] - mean) * rstd * g1.z + be1.z;
    o1.w = (v[7] - mean) * rstd * g1.w + be1.w;
    __stcs((float4*)(out + (size_t)n * Dd + lane * 8), o0);
    __stcs((float4*)(out + (size_t)n * Dd + lane * 8 + 4), o1);
}

// ---------------- stream/event singletons (created at load, outside capture)
namespace {
struct GpuRes {
    cudaStream_t s2;
    cudaEvent_t evF, evJ;
    GpuRes() {
        cudaStreamCreateWithFlags(&s2, cudaStreamNonBlocking);
        cudaEventCreateWithFlags(&evF, cudaEventDisableTiming);
        cudaEventCreateWithFlags(&evJ, cudaEventDisableTiming);
    }
};
GpuRes g_res;
}

// ---------------------------------------------------------------------------
extern "C" void kernel_launch(void* const* d_in, const int* in_sizes, int n_in,
                              void* d_out, int out_size) {
    const float* x = (const float*)d_in[0];
    const int* ei = (const int*)d_in[1];
    const float* W = (const float*)d_in[2];
    const float* att_src = (const float*)d_in[3];
    const float* att_dst = (const float*)d_in[4];
    const float* bias = (const float*)d_in[5];
    const float* gamma = (const float*)d_in[6];
    const float* beta = (const float*)d_in[7];
    float* out = (float*)d_out;

    // fork: CSR build on side stream, concurrent with GEMM on main stream
    cudaEventRecord(g_res.evF, 0);
    cudaStreamWaitEvent(g_res.s2, g_res.evF, 0);
    degree_kernel<<<(Ee + 255) / 256, 256, 0, g_res.s2>>>(ei);
    scan_kernel<<<1, 1024, 0, g_res.s2>>>();
    scatter_kernel<<<(Ee + 255) / 256, 256, 0, g_res.s2>>>(ei);
    cudaEventRecord(g_res.evJ, g_res.s2);

    gemm_att_kernel<<<dim3((Nn + 127) / 128, 2), 256>>>(x, W, att_src, att_dst);

    // join, then pipelined gather
    cudaStreamWaitEvent(0, g_res.evJ, 0);
    gather_kernel<<<(Nn + 7) / 8, 256>>>(bias, gamma, beta, out);
}

// round 10
// speedup vs baseline: 1.9170x; 1.9170x over previous
#include <cuda_runtime.h>
#include <cuda_fp16.h>
#include <cooperative_groups.h>
#include <math.h>

namespace cg = cooperative_groups;

#define Nn 100000
#define Ee 1600000
#define Kin 128
#define Dd 256
#define CSB 148   // cooperative scan/scatter blocks

// ---------------- scratch (device globals: no allocation allowed) ----------
__device__ __half g_h16[(size_t)Nn * Dd];  // 51.2 MB projected features (fp16)
__device__ float g_as[Nn * 4];             // a_src per node/head
__device__ float g_ad[Nn * 4];             // a_dst per node/head
__device__ int   g_deg[Nn];                // zero-init; scanscatter re-zeroes
__device__ int   g_off[Nn + 1];
__device__ int   g_cur[Nn];
__device__ int   g_csr[Ee];                // src ids grouped by dst
__device__ int   g_bsum[CSB];
__device__ int   g_boff[CSB];

// ---------------- helpers ---------------------------------------------------
__device__ __forceinline__ float lrelu(float v) { return v > 0.f ? v : 0.2f * v; }
__device__ __forceinline__ float selh(const float4& v, int h) {
    return h == 0 ? v.x : (h == 1 ? v.y : (h == 2 ? v.z : v.w));
}
__device__ __forceinline__ void accum8(float* acc, const uint4& hv, float a) {
    float2 f;
    f = __half22float2(*(const __half2*)&hv.x); acc[0] += f.x * a; acc[1] += f.y * a;
    f = __half22float2(*(const __half2*)&hv.y); acc[2] += f.x * a; acc[3] += f.y * a;
    f = __half22float2(*(const __half2*)&hv.z); acc[4] += f.x * a; acc[5] += f.y * a;
    f = __half22float2(*(const __half2*)&hv.w); acc[6] += f.x * a; acc[7] += f.y * a;
}
__device__ __forceinline__ unsigned int to_tf32(float f) {
    unsigned int r;
    asm("cvt.rna.tf32.f32 %0, %1;" : "=r"(r) : "f"(f));
    return r;
}
__device__ __forceinline__ void mma_tf32(float* c,
                                         const unsigned int* a,
                                         const unsigned int* b) {
    asm volatile(
        "mma.sync.aligned.m16n8k8.row.col.f32.tf32.tf32.f32 "
        "{%0,%1,%2,%3}, {%4,%5,%6,%7}, {%8,%9}, {%0,%1,%2,%3};"
        : "+f"(c[0]), "+f"(c[1]), "+f"(c[2]), "+f"(c[3])
        : "r"(a[0]), "r"(a[1]), "r"(a[2]), "r"(a[3]),
          "r"(b[0]), "r"(b[1]));
}

// ---------------- degree count (coalesced, grid-strided) --------------------
__global__ void degree_kernel(const int* __restrict__ ei) {
    int e = blockIdx.x * blockDim.x + threadIdx.x;
    if (e < Ee) atomicAdd(&g_deg[ei[Ee + e]], 1);
}

// ---------------- cooperative scan + scatter (coalesced) --------------------
__global__ void scanscatter_kernel(const int* __restrict__ ei) {
    cg::grid_group grid = cg::this_grid();
    const int b = blockIdx.x, t = threadIdx.x;
    const int NPB = (Nn + CSB - 1) / CSB;      // 676 nodes per block
    const int n0 = b * NPB;
    const int n1 = min(n0 + NPB, Nn);

    __shared__ int sscan[1024];
    __shared__ int sb[CSB + 1];

    // phase 1: block-local degree sum (coalesced reads)
    int v = 0;
    for (int idx = n0 + t; idx < n1; idx += 1024) v += g_deg[idx];
    sscan[t] = v;
    __syncthreads();
    for (int off = 512; off; off >>= 1) {
        if (t < off) sscan[t] += sscan[t + off];
        __syncthreads();
    }
    if (t == 0) g_bsum[b] = sscan[0];
    grid.sync();

    // phase 2: block 0 scans the per-block sums (exclusive)
    if (b == 0) {
        if (t < CSB) sb[t] = g_bsum[t];
        __syncthreads();
        if (t == 0) {
            int run = 0;
            for (int i = 0; i < CSB; ++i) { int x = sb[i]; sb[i] = run; run += x; }
            sb[CSB] = run;
        }
        __syncthreads();
        if (t < CSB) g_boff[t] = sb[t];
        if (t == 0) g_off[Nn] = sb[CSB];
    }
    grid.sync();

    // phase 3: per-node exclusive scan within block (coalesced tiles)
    int run = g_boff[b];
    for (int base = n0; base < n1; base += 1024) {
        const int idx = base + t;
        const int d = (idx < n1) ? g_deg[idx] : 0;
        sscan[t] = d;
        __syncthreads();
        for (int off = 1; off < 1024; off <<= 1) {
            int add = (t >= off) ? sscan[t - off] : 0;
            __syncthreads();
            sscan[t] += add;
            __syncthreads();
        }
        if (idx < n1) {
            const int excl = run + sscan[t] - d;
            g_off[idx] = excl;
            g_cur[idx] = excl;
            g_deg[idx] = 0;   // ready for next call
        }
        const int tot = sscan[1023];
        __syncthreads();
        run += tot;
    }
    grid.sync();

    // phase 4: scatter (coalesced edge reads, grid-strided)
    const int stride = CSB * 1024;
    for (int e = b * 1024 + t; e < Ee; e += stride) {
        const int s = ei[e];
        const int d2 = ei[Ee + e];
        const int pos = atomicAdd(&g_cur[d2], 1);
        g_csr[pos] = s;
    }
}

// ---------------- tf32 tensor GEMM + fused attention dots -------------------
__global__ __launch_bounds__(256, 2)
void gemm_att_kernel(const float* __restrict__ x, const float* __restrict__ W,
                     const float* __restrict__ att_src,
                     const float* __restrict__ att_dst) {
    __shared__ float xs[128][36];   // [m][k]
    __shared__ float ws[32][136];   // [k][n]
    const int m0 = blockIdx.x * 128;
    const int c0 = blockIdx.y * 128;
    const int tid = threadIdx.x;
    const int warp = tid >> 5, lane = tid & 31;
    const int g = lane >> 2, tig = lane & 3;
    const int wm = (warp & 3) * 32;
    const int wn = (warp >> 2) * 64;

    float acc[2][8][4];
    #pragma unroll
    for (int mt = 0; mt < 2; ++mt)
        #pragma unroll
        for (int nn = 0; nn < 8; ++nn)
            #pragma unroll
            for (int j = 0; j < 4; ++j) acc[mt][nn][j] = 0.f;

    const int xr = tid >> 1, xc = (tid & 1) * 16;
    const int wk = tid >> 3, wc = (tid & 7) * 16;

    for (int kt = 0; kt < 4; ++kt) {
        float4 xv[4], wv[4];
        #pragma unroll
        for (int i = 0; i < 4; ++i) {
            xv[i] = make_float4(0.f, 0.f, 0.f, 0.f);
            if (m0 + xr < Nn)
                xv[i] = *(const float4*)(x + (size_t)(m0 + xr) * Kin + kt * 32 + xc + i * 4);
            wv[i] = *(const float4*)(W + (size_t)(kt * 32 + wk) * Dd + c0 + wc + i * 4);
        }
        __syncthreads();
        #pragma unroll
        for (int i = 0; i < 4; ++i) {
            *(float4*)&xs[xr][xc + i * 4] = xv[i];
            *(float4*)&ws[wk][wc + i * 4] = wv[i];
        }
        __syncthreads();

        #pragma unroll
        for (int ks = 0; ks < 4; ++ks) {
            const int kb = ks * 8;
            unsigned int a[2][4], b[8][2];
            #pragma unroll
            for (int mt = 0; mt < 2; ++mt) {
                const int r = wm + mt * 16 + g;
                a[mt][0] = to_tf32(xs[r][kb + tig]);
                a[mt][1] = to_tf32(xs[r + 8][kb + tig]);
                a[mt][2] = to_tf32(xs[r][kb + tig + 4]);
                a[mt][3] = to_tf32(xs[r + 8][kb + tig + 4]);
            }
            #pragma unroll
            for (int nn = 0; nn < 8; ++nn) {
                const int c = wn + nn * 8 + g;
                b[nn][0] = to_tf32(ws[kb + tig][c]);
                b[nn][1] = to_tf32(ws[kb + tig + 4][c]);
            }
            #pragma unroll
            for (int mt = 0; mt < 2; ++mt)
                #pragma unroll
                for (int nn = 0; nn < 8; ++nn)
                    mma_tf32(acc[mt][nn], a[mt], b[nn]);
        }
    }

    const int head = blockIdx.y * 2 + (warp >> 2);
    #pragma unroll
    for (int mt = 0; mt < 2; ++mt) {
        const int r0 = m0 + wm + mt * 16 + g;
        const int r1 = r0 + 8;
        float s0 = 0.f, d0 = 0.f, s1 = 0.f, d1 = 0.f;
        #pragma unroll
        for (int nn = 0; nn < 8; ++nn) {
            const int cl = nn * 8 + tig * 2;
            const float as0 = att_src[head * 64 + cl];
            const float as1 = att_src[head * 64 + cl + 1];
            const float ad0 = att_dst[head * 64 + cl];
            const float ad1 = att_dst[head * 64 + cl + 1];
            const float* cc = acc[mt][nn];
            s0 += cc[0] * as0 + cc[1] * as1;
            d0 += cc[0] * ad0 + cc[1] * ad1;
            s1 += cc[2] * as0 + cc[3] * as1;
            d1 += cc[2] * ad0 + cc[3] * ad1;
            const int gc = c0 + wn + cl;
            if (r0 < Nn)
                *(__half2*)(g_h16 + (size_t)r0 * Dd + gc) = __floats2half2_rn(cc[0], cc[1]);
            if (r1 < Nn)
                *(__half2*)(g_h16 + (size_t)r1 * Dd + gc) = __floats2half2_rn(cc[2], cc[3]);
        }
        #pragma unroll
        for (int o = 1; o <= 2; o <<= 1) {
            s0 += __shfl_xor_sync(0xffffffffu, s0, o);
            d0 += __shfl_xor_sync(0xffffffffu, d0, o);
            s1 += __shfl_xor_sync(0xffffffffu, s1, o);
            d1 += __shfl_xor_sync(0xffffffffu, d1, o);
        }
        if (tig == 0) {
            if (r0 < Nn) { g_as[r0 * 4 + head] = s0; g_ad[r0 * 4 + head] = d0; }
            if (r1 < Nn) { g_as[r1 * 4 + head] = s1; g_ad[r1 * 4 + head] = d1; }
        }
    }
}

// ---------------- single-pass gather (R8 best) -------------------------------
__global__ void gather_kernel(const float* __restrict__ bias,
                              const float* __restrict__ gamma,
                              const float* __restrict__ beta,
                              float* __restrict__ out) {
    const int w = threadIdx.x >> 5;
    const int lane = threadIdx.x & 31;
    const int n = blockIdx.x * 8 + w;
    if (n >= Nn) return;

    const int hL = lane >> 3;   // lane owns channels [lane*8, +8) = one head
    const float4 as4 = *(const float4*)(g_as + n * 4);
    const float4 ad4 = *(const float4*)(g_ad + n * 4);
    const float adL = selh(ad4, hL);
    const int off0 = g_off[n], off1 = g_off[n + 1];

    const __half* hbase = g_h16;
    const size_t laneoff = (size_t)lane * 8;

    float acc[8] = {0.f, 0.f, 0.f, 0.f, 0.f, 0.f, 0.f, 0.f};
    float den;
    {   // self loop
        den = __expf(lrelu(selh(as4, hL) + adL));
        uint4 hv = *(const uint4*)(hbase + (size_t)n * Dd + laneoff);
        accum8(acc, hv, den);
    }

    int i = off0;
    for (; i + 4 <= off1; i += 4) {
        const int s0i = g_csr[i], s1i = g_csr[i + 1];
        const int s2i = g_csr[i + 2], s3i = g_csr[i + 3];
        const float4 p0 = *(const float4*)(g_as + s0i * 4);
        const float4 p1 = *(const float4*)(g_as + s1i * 4);
        const float4 p2 = *(const float4*)(g_as + s2i * 4);
        const float4 p3 = *(const float4*)(g_as + s3i * 4);
        const uint4 v0 = *(const uint4*)(hbase + (size_t)s0i * Dd + laneoff);
        const uint4 v1 = *(const uint4*)(hbase + (size_t)s1i * Dd + laneoff);
        const uint4 v2 = *(const uint4*)(hbase + (size_t)s2i * Dd + laneoff);
        const uint4 v3 = *(const uint4*)(hbase + (size_t)s3i * Dd + laneoff);
        const float a0 = __expf(lrelu(selh(p0, hL) + adL));
        const float a1 = __expf(lrelu(selh(p1, hL) + adL));
        const float a2 = __expf(lrelu(selh(p2, hL) + adL));
        const float a3 = __expf(lrelu(selh(p3, hL) + adL));
        den += a0 + a1 + a2 + a3;
        accum8(acc, v0, a0);
        accum8(acc, v1, a1);
        accum8(acc, v2, a2);
        accum8(acc, v3, a3);
    }
    for (; i < off1; ++i) {
        const int src = g_csr[i];
        const float4 p = *(const float4*)(g_as + src * 4);
        const uint4 v = *(const uint4*)(hbase + (size_t)src * Dd + laneoff);
        const float a = __expf(lrelu(selh(p, hL) + adL));
        den += a;
        accum8(acc, v, a);
    }

    const float rdL = 1.f / den;

    // ---- epilogue: bias + ELU + LayerNorm ----
    const float4 b0 = *(const float4*)(bias + lane * 8);
    const float4 b1 = *(const float4*)(bias + lane * 8 + 4);
    float v[8];
    v[0] = acc[0] * rdL + b0.x; v[1] = acc[1] * rdL + b0.y;
    v[2] = acc[2] * rdL + b0.z; v[3] = acc[3] * rdL + b0.w;
    v[4] = acc[4] * rdL + b1.x; v[5] = acc[5] * rdL + b1.y;
    v[6] = acc[6] * rdL + b1.z; v[7] = acc[7] * rdL + b1.w;
    float sum = 0.f, sq = 0.f;
    #pragma unroll
    for (int j = 0; j < 8; ++j) {
        v[j] = v[j] > 0.f ? v[j] : expm1f(v[j]);
        sum += v[j];
        sq += v[j] * v[j];
    }
    #pragma unroll
    for (int o = 16; o; o >>= 1) {
        sum += __shfl_xor_sync(0xffffffffu, sum, o);
        sq  += __shfl_xor_sync(0xffffffffu, sq, o);
    }
    const float mean = sum * (1.f / 256.f);
    const float var = sq * (1.f / 256.f) - mean * mean;
    const float rstd = rsqrtf(var + 1e-5f);

    const float4 g0 = *(const float4*)(gamma + lane * 8);
    const float4 g1 = *(const float4*)(gamma + lane * 8 + 4);
    const float4 be0 = *(const float4*)(beta + lane * 8);
    const float4 be1 = *(const float4*)(beta + lane * 8 + 4);
    float4 o0, o1;
    o0.x = (v[0] - mean) * rstd * g0.x + be0.x;
    o0.y = (v[1] - mean) * rstd * g0.y + be0.y;
    o0.z = (v[2] - mean) * rstd * g0.z + be0.z;
    o0.w = (v[3] - mean) * rstd * g0.w + be0.w;
    o1.x = (v[4] - mean) * rstd * g1.x + be1.x;
    o1.y = (v[5] - mean) * rstd * g1.y + be1.y;
    o1.z = (v[6] - mean) * rstd * g1.z + be1.z;
    o1.w = (v[7] - mean) * rstd * g1.w + be1.w;
    __stcs((float4*)(out + (size_t)n * Dd + lane * 8), o0);
    __stcs((float4*)(out + (size_t)n * Dd + lane * 8 + 4), o1);
}

// ---------------- stream/event singletons (created at load, outside capture)
namespace {
struct GpuRes {
    cudaStream_t s2;
    cudaEvent_t evF, evJ;
    GpuRes() {
        cudaStreamCreateWithFlags(&s2, cudaStreamNonBlocking);
        cudaEventCreateWithFlags(&evF, cudaEventDisableTiming);
        cudaEventCreateWithFlags(&evJ, cudaEventDisableTiming);
    }
};
GpuRes g_res;
}

// ---------------------------------------------------------------------------
extern "C" void kernel_launch(void* const* d_in, const int* in_sizes, int n_in,
                              void* d_out, int out_size) {
    const float* x = (const float*)d_in[0];
    const int* ei = (const int*)d_in[1];
    const float* W = (const float*)d_in[2];
    const float* att_src = (const float*)d_in[3];
    const float* att_dst = (const float*)d_in[4];
    const float* bias = (const float*)d_in[5];
    const float* gamma = (const float*)d_in[6];
    const float* beta = (const float*)d_in[7];
    float* out = (float*)d_out;

    // fork: CSR build on side stream, concurrent with GEMM on main stream
    cudaEventRecord(g_res.evF, 0);
    cudaStreamWaitEvent(g_res.s2, g_res.evF, 0);
    degree_kernel<<<(Ee + 255) / 256, 256, 0, g_res.s2>>>(ei);            // launch #1
    {
        const int* ei_arg = ei;
        void* args[] = { (void*)&ei_arg };
        cudaLaunchCooperativeKernel((void*)scanscatter_kernel, dim3(CSB), // launch #2
                                    dim3(1024), args, 0, g_res.s2);
    }
    cudaEventRecord(g_res.evJ, g_res.s2);

    gemm_att_kernel<<<dim3((Nn + 127) / 128, 2), 256>>>(x, W, att_src, att_dst); // #3

    // join, then single-pass gather (launch #4 -> ncu capture slot)
    cudaStreamWaitEvent(0, g_res.evJ, 0);
    gather_kernel<<<(Nn + 7) / 8, 256>>>(bias, gamma, beta, out);
}